// round 17
// baseline (speedup 1.0000x reference)
#include <cuda_runtime.h>
#include <cuda.h>
#include <cuda_bf16.h>
#include <cstdint>
#include <cstdio>

// ============================================================================
// QuantizedLinear via two-digit int8 tcgen05 GEMM, persistent cg2 clusters,
// with PREP FUSED into the GEMM kernel behind progress gates.
//   out[t,o] = (sum_k x[t,k]*(w[o,k]-zp[o])) * scale[o] + bias[o]
//   M=TOKENS=4096, N=OUT_F=11008, K=IN_F=4096
//
// W int8-exact. x fixed-point per row: x ~= s_row*(128*h + l), h,l in s8.
// Two kind::i8 GEMMs (s32 in TMEM): D1 (cols 0-255), D0 (cols 256-511).
// out = (s_row*(128*D1+D0) - zp*rowsum)*scale + bias.
//
// Single persistent kernel, 148 CTAs = 74 cg2 pairs, static tiles
// t = pair + 74*ti (mp = t&15, nt = t>>4). PREP PHASE inside the kernel:
//   - x-quant: all 6 warps, rows r = cta + 148*i; per-256-row-group counters.
//   - W-pack: epilogue warps (0-3) only, 43 N-groups in order, each CTA packs
//     1/148 of each group; per-group counters.
// Producer gates each tile's TMA on g_xdone[mp]==256 && g_wdone[nt]==148
// (acquire + fence.proxy.async), so GEMM ramps ~13us in while the rest of
// W-pack overlaps with GEMM compute.
// Warps: 0-3 prep+epilogue, 4 producer, 5 MMA driver (leader CTA).
// ============================================================================

#define TOKENS 4096
#define IN_F   4096
#define OUT_F  11008

#define BN    256               // N per pair-tile (one N=256 MMA region)
#define KC    64
#define NCH   (IN_F / KC)       // 64 chunks per tile
#define NST   9                 // pipeline stages
#define NPAIR 74
#define NUNIT 688               // 16 M-pairs x 43 N-tiles
#define NWG   43                // W pack groups (256 out-rows each)
#define WG_E  262144            // int4 loads per W group (256*4096/4)
#define WG_PER 1772             // per-CTA slice of a W group (ceil)

#if defined(__CUDA_ARCH__) && (defined(__CUDA_ARCH_FEAT_SM100_ALL) || defined(__CUDA_ARCH_FEAT_SM103_ALL) || defined(__CUDA_ARCH_FEAT_SM101_ALL))
#define HAVE_TCGEN05 1
#else
#define HAVE_TCGEN05 0
#endif

// ---- dynamic SMEM layout (per CTA) ----
#define OFF_TMEM     0
#define OFF_FULL(s)  (16 + 8*(s))     // 16..88
#define OFF_EMPTY(s) (96 + 8*(s))     // 96..168
#define OFF_DONE     176
#define OFF_EPIF     184
#define STAGE_STRIDE 24576            // AH 8K + AL 8K + B 8K (int8)
#define OFF_ST(s)    (1024 + (s)*STAGE_STRIDE)
#define ST_AH        0
#define ST_AL        8192
#define ST_B         16384
#define OFF_PRM      (1024 + NST*STAGE_STRIDE)   // 222208
#define SMEM_TOTAL   (OFF_PRM + 3*BN*4)          // 225280

// idesc kind::i8 cg2: c=S32(2)@[4:6), a=S8(1)@[7:10), b=S8(1)@[10:13),
// N/8 @[17:23), M_total/16 @[24:29)
#define MMA_IDESC ((2u<<4) | (1u<<7) | (1u<<10) | ((BN/8)<<17) | ((256/16)<<24))

// ---- scratch (device globals: no allocation allowed) ----
__device__ __align__(1024) int8_t g_W8[(size_t)OUT_F  * IN_F];
__device__ __align__(1024) int8_t g_Ah[(size_t)TOKENS * IN_F];
__device__ __align__(1024) int8_t g_Al[(size_t)TOKENS * IN_F];
__device__ float g_rowsum[TOKENS];
__device__ float g_rscale[TOKENS];
__device__ int   g_wdone[NWG];     // W group counters (148 = done)
__device__ int   g_xdone[16];      // x 256-row-group counters (256 = done)

// ============================================================================
// Common helpers
// ============================================================================
__device__ __forceinline__ uint32_t smem_u32(const void* p) {
    uint32_t a;
    asm("{ .reg .u64 t; cvta.to.shared.u64 t, %1; cvt.u32.u64 %0, t; }"
        : "=r"(a) : "l"(p));
    return a;
}

__device__ __forceinline__ int ld_acquire(const int* p) {
    int v;
    asm volatile("ld.acquire.gpu.global.b32 %0, [%1];" : "=r"(v) : "l"(p) : "memory");
    return v;
}

// ============================================================================
// Counter zeroing kernel (runs first; graph-replay safe reset)
// ============================================================================
__global__ void k_zero() {
    int t = threadIdx.x;
    if (t < NWG) g_wdone[t] = 0;
    if (t < 16)  g_xdone[t] = 0;
}

// ============================================================================
// tcgen05 PTX helpers (guarded)
// ============================================================================
#if HAVE_TCGEN05
#define MBAR_INIT(addr, cnt) \
    asm volatile("mbarrier.init.shared.b64 [%0], %1;" :: "r"(addr), "r"((uint32_t)(cnt)) : "memory")
#define MBAR_EXPECT(addr, bytes) \
    asm volatile("mbarrier.arrive.expect_tx.shared.b64 _, [%0], %1;" :: "r"(addr), "r"((uint32_t)(bytes)) : "memory")

__device__ __forceinline__ void mbar_wait(uint32_t addr, uint32_t parity) {
    uint32_t done;
    asm volatile(
        "{\n\t.reg .pred p;\n\t"
        "mbarrier.try_wait.parity.acquire.cta.shared::cta.b64 p, [%1], %2;\n\t"
        "selp.b32 %0, 1, 0, p;\n\t}"
        : "=r"(done) : "r"(addr), "r"(parity) : "memory");
    if (!done) {
        asm volatile(
            "{\n\t.reg .pred P1;\n\t"
            "WL_%=:\n\t"
            "mbarrier.try_wait.parity.acquire.cta.shared::cta.b64 P1, [%0], %1, 0x989680;\n\t"
            "@P1 bra.uni WD_%=;\n\t"
            "bra.uni WL_%=;\n\t"
            "WD_%=:\n\t}"
            :: "r"(addr), "r"(parity) : "memory");
    }
}

// relaxed wait: ONLY for waits whose post-wait SMEM accesses are async-proxy
__device__ __forceinline__ void mbar_wait_relaxed(uint32_t addr, uint32_t parity) {
    uint32_t done;
    asm volatile(
        "{\n\t.reg .pred p;\n\t"
        "mbarrier.try_wait.parity.relaxed.cta.shared::cta.b64 p, [%1], %2;\n\t"
        "selp.b32 %0, 1, 0, p;\n\t}"
        : "=r"(done) : "r"(addr), "r"(parity) : "memory");
    if (!done) {
        asm volatile(
            "{\n\t.reg .pred P1;\n\t"
            "RL_%=:\n\t"
            "mbarrier.try_wait.parity.relaxed.cta.shared::cta.b64 P1, [%0], %1, 0x989680;\n\t"
            "@P1 bra.uni RD_%=;\n\t"
            "bra.uni RL_%=;\n\t"
            "RD_%=:\n\t}"
            :: "r"(addr), "r"(parity) : "memory");
    }
}

// cg2 TMA 3D load: both CTAs execute; complete_tx targets leader CTA's barrier
// via Sm100MmaPeerBitMask (clear bit 24 of the local barrier address).
__device__ __forceinline__ void tma_ld_cg2(uint32_t smem, const void* map,
                                           int x, int y, uint32_t mbar) {
    asm volatile(
        "{\n\t.reg .b32 lb;\n\t"
        "and.b32 lb, %5, 0xFEFFFFFF;\n\t"
        "cp.async.bulk.tensor.3d.cta_group::2.shared::cluster.global"
        ".tile.mbarrier::complete_tx::bytes [%0], [%1, {%2, %3, %4}], [lb];\n\t}"
        :: "r"(smem), "l"(map), "r"(x), "r"(y), "r"(0), "r"(mbar) : "memory");
}

// K-major SW64 smem descriptor: layout=4 (SW64), version=1, SBO=32, LBO=1
__device__ __forceinline__ uint64_t mk_desc64(uint32_t addr) {
    const uint64_t BASE = (4ull << 61) | (1ull << 46) | (32ull << 32) | (1ull << 16);
    return BASE | ((uint64_t)(addr >> 4) & 0x3FFF);
}

__device__ __forceinline__ void mma_i8_ss_cg2(uint32_t d, uint64_t a, uint64_t b,
                                              uint32_t idesc, uint32_t en) {
    asm volatile(
        "{\n\t.reg .pred p;\n\t"
        "setp.ne.u32 p, %4, 0;\n\t"
        "tcgen05.mma.cta_group::2.kind::i8 [%0], %1, %2, %3, "
        "{%5, %5, %5, %5, %5, %5, %5, %5}, p;\n\t}"
        :: "r"(d), "l"(a), "l"(b), "r"(idesc), "r"(en), "r"(0u) : "memory");
}

__device__ __forceinline__ void tc_commit_mc2(uint32_t mbar) {
    asm volatile(
        "tcgen05.commit.cta_group::2.mbarrier::arrive::one.shared::cluster"
        ".multicast::cluster.b64 [%0], %1;"
        :: "r"(mbar), "h"((uint16_t)0x3) : "memory");
}

// arrive (cluster-scope) on target rank's mbarrier at same smem offset
__device__ __forceinline__ void mbar_arrive_rank(uint32_t addr, int trank) {
    asm volatile(
        "{\n\t.reg .b32 ra;\n\t"
        "mapa.shared::cluster.u32 ra, %0, %1;\n\t"
        "mbarrier.arrive.shared::cluster.b64 _, [ra];\n\t}"
        :: "r"(addr), "r"(trank) : "memory");
}

#define TC_LD_X32(r, tmem_addr) \
    asm volatile( \
        "tcgen05.ld.sync.aligned.32x32b.x32.b32 " \
        "{%0, %1, %2, %3, %4, %5, %6, %7, " \
        " %8, %9, %10, %11, %12, %13, %14, %15, " \
        " %16, %17, %18, %19, %20, %21, %22, %23, " \
        " %24, %25, %26, %27, %28, %29, %30, %31}, [%32];" \
        : "=r"((r)[0]),  "=r"((r)[1]),  "=r"((r)[2]),  "=r"((r)[3]), \
          "=r"((r)[4]),  "=r"((r)[5]),  "=r"((r)[6]),  "=r"((r)[7]), \
          "=r"((r)[8]),  "=r"((r)[9]),  "=r"((r)[10]), "=r"((r)[11]), \
          "=r"((r)[12]), "=r"((r)[13]), "=r"((r)[14]), "=r"((r)[15]), \
          "=r"((r)[16]), "=r"((r)[17]), "=r"((r)[18]), "=r"((r)[19]), \
          "=r"((r)[20]), "=r"((r)[21]), "=r"((r)[22]), "=r"((r)[23]), \
          "=r"((r)[24]), "=r"((r)[25]), "=r"((r)[26]), "=r"((r)[27]), \
          "=r"((r)[28]), "=r"((r)[29]), "=r"((r)[30]), "=r"((r)[31]) \
        : "r"(tmem_addr))

#define CLUSTER_SYNC_() do { \
    asm volatile("barrier.cluster.arrive.aligned;" ::: "memory"); \
    asm volatile("barrier.cluster.wait.aligned;" ::: "memory"); \
} while (0)
#endif  // HAVE_TCGEN05

// ============================================================================
// Fused persistent kernel
// ============================================================================
__global__ void __launch_bounds__(192, 1) __cluster_dims__(2, 1, 1) qlinear_fused(
    const __grid_constant__ CUtensorMap tmAh,
    const __grid_constant__ CUtensorMap tmAl,
    const __grid_constant__ CUtensorMap tmB,
    const int4*  __restrict__ w_src,      // raw int32 weights
    const float4* __restrict__ x_src,     // raw fp32 input
    const float* __restrict__ scales,
    const float* __restrict__ zps,
    const float* __restrict__ biasv,
    float* __restrict__ out)
{
#if HAVE_TCGEN05
    extern __shared__ __align__(1024) char smem[];
    const uint32_t sb = smem_u32(smem);
    const int tid  = threadIdx.x;
    const int wid  = tid >> 5;
    const int lane = tid & 31;
    const int rank = blockIdx.x & 1;           // cg2 pair rank
    const int pair = blockIdx.x >> 1;          // 0..73
    const int cta  = blockIdx.x;               // 0..147
    const int ntiles = (NUNIT - pair + NPAIR - 1) / NPAIR;

    if (wid == 0) {
        asm volatile("tcgen05.alloc.cta_group::2.sync.aligned.shared::cta.b32 [%0], %1;"
                     :: "r"(sb + OFF_TMEM), "r"(512u) : "memory");
        asm volatile("tcgen05.relinquish_alloc_permit.cta_group::2.sync.aligned;");
    }
    if (tid == 0) {
        for (int s = 0; s < NST; s++) {
            MBAR_INIT(sb + OFF_FULL(s), 1);
            MBAR_INIT(sb + OFF_EMPTY(s), 1);
        }
        MBAR_INIT(sb + OFF_DONE, 1);
        MBAR_INIT(sb + OFF_EPIF, 2);      // one arrive per CTA's epilogue
        asm volatile("fence.proxy.async.shared::cta;" ::: "memory");
    }
    __syncthreads();
    CLUSTER_SYNC_();   // peer barriers must be live before cg2 TMA / commits

    uint32_t tmem;
    asm volatile("ld.shared.b32 %0, [%1];" : "=r"(tmem) : "r"(sb + OFF_TMEM));

    // ======================= PREP PHASE 1: x quant (all 6 warps) ============
    {
        __shared__ float redM[6], redS[6], bc[1];
        for (int r = cta; r < TOKENS; r += 148) {
            const float4* px = x_src + (size_t)r * (IN_F / 4);
            float mx = 0.f, sm = 0.f;
            for (int i = tid; i < IN_F / 4; i += 192) {
                float4 v = px[i];
                mx = fmaxf(mx, fmaxf(fmaxf(fabsf(v.x), fabsf(v.y)),
                                     fmaxf(fabsf(v.z), fabsf(v.w))));
                sm += v.x + v.y + v.z + v.w;
            }
#pragma unroll
            for (int o = 16; o > 0; o >>= 1) {
                mx = fmaxf(mx, __shfl_xor_sync(0xffffffffu, mx, o));
                sm += __shfl_xor_sync(0xffffffffu, sm, o);
            }
            if (lane == 0) { redM[wid] = mx; redS[wid] = sm; }
            __syncthreads();
            if (tid == 0) {
                float m = redM[0], s = redS[0];
#pragma unroll
                for (int q = 1; q < 6; q++) { m = fmaxf(m, redM[q]); s += redS[q]; }
                bc[0]       = (m > 1e-30f) ? (16000.f / m) : 0.f;
                g_rowsum[r] = s;
                g_rscale[r] = (m > 1e-30f) ? (m / 16000.f) : 0.f;
            }
            __syncthreads();
            const float inv = bc[0];
            char4* ph = (char4*)g_Ah + (size_t)r * (IN_F / 4);
            char4* pl = (char4*)g_Al + (size_t)r * (IN_F / 4);
            for (int i = tid; i < IN_F / 4; i += 192) {
                float4 v = px[i];
                const float* f = &v.x;
                signed char hd[4], ld8[4];
#pragma unroll
                for (int j = 0; j < 4; j++) {
                    int vq = __float2int_rn(f[j] * inv);   // |vq| <= 16000
                    int h  = (vq + 64) >> 7;               // |h| <= 126
                    int l  = vq - (h << 7);                // in [-64, 63]
                    hd[j]  = (signed char)h;
                    ld8[j] = (signed char)l;
                }
                ph[i] = make_char4(hd[0], hd[1], hd[2], hd[3]);
                pl[i] = make_char4(ld8[0], ld8[1], ld8[2], ld8[3]);
            }
            __syncthreads();   // quant stores done before arrive
            if (tid == 0) { __threadfence(); atomicAdd(&g_xdone[r >> 8], 1); }
        }
    }
    __syncthreads();   // warps 4,5 leave prep; warps 0-3 continue with W pack

    // ---------------- producer warp (warp 4, lane 0, BOTH CTAs) ----------------
    if (wid == 4 && lane == 0) {
        int s = 0, k = 0;
        for (int ti = 0; ti < ntiles; ti++) {
            const int t  = pair + ti * NPAIR;
            const int mp = t & 15, nt = t >> 4;
            // gate on prep progress (immediate once groups are packed)
            while (ld_acquire(&g_xdone[mp]) < 256) {}
            while (ld_acquire(&g_wdone[nt]) < 148) {}
            asm volatile("fence.proxy.async;" ::: "memory");
            const int rb = mp * 256 + rank * 128;     // A rows (this CTA)
            const int cb = nt * 256 + rank * 128;     // B rows (this CTA)
            for (int c = 0; c < NCH; c++) {
                if (k > 0) mbar_wait_relaxed(sb + OFF_EMPTY(s), (k - 1) & 1);
                if (rank == 0) MBAR_EXPECT(sb + OFF_FULL(s), 2u * STAGE_STRIDE);
                const uint32_t st = sb + OFF_ST(s);
                const uint32_t fb = sb + OFF_FULL(s);
                tma_ld_cg2(st + ST_AH, &tmAh, c * KC, rb, fb);
                tma_ld_cg2(st + ST_AL, &tmAl, c * KC, rb, fb);
                tma_ld_cg2(st + ST_B,  &tmB,  c * KC, cb, fb);
                if (++s == NST) { s = 0; k++; }
            }
        }
    }

    // ---------------- MMA driver (leader CTA, warp 5, lane 0) ----------------
    if (rank == 0 && wid == 5 && lane == 0) {
        int s = 0, k = 0;
        for (int ti = 0; ti < ntiles; ti++) {
            if (ti > 0) {   // both CTAs' epilogues must have DRAINED tile ti-1
                mbar_wait(sb + OFF_EPIF, (ti - 1) & 1);
                asm volatile("tcgen05.fence::after_thread_sync;" ::: "memory");
            }
            for (int c = 0; c < NCH; c++) {
                mbar_wait_relaxed(sb + OFF_FULL(s), k & 1);
                const uint32_t st = sb + OFF_ST(s);
                const uint64_t ah = mk_desc64(st + ST_AH);
                const uint64_t al = mk_desc64(st + ST_AL);
                const uint64_t bd = mk_desc64(st + ST_B);
                const uint32_t en0 = (c > 0) ? 1u : 0u;
                // K=32 int8 per dispatch = 32B = +2 desc units
                mma_i8_ss_cg2(tmem,       ah,     bd,     MMA_IDESC, en0);
                mma_i8_ss_cg2(tmem,       ah + 2, bd + 2, MMA_IDESC, 1u);
                mma_i8_ss_cg2(tmem + 256, al,     bd,     MMA_IDESC, en0);
                mma_i8_ss_cg2(tmem + 256, al + 2, bd + 2, MMA_IDESC, 1u);
                tc_commit_mc2(sb + OFF_EMPTY(s));
                if (c == NCH - 1) tc_commit_mc2(sb + OFF_DONE);
                if (++s == NST) { s = 0; k++; }
            }
        }
    }

    // ---------------- warps 0-3: W pack, then epilogue loop -------------------
    if (wid < 4) {
        // ======================= PREP PHASE 2: W pack (43 groups) =============
        {
            const int start = cta * WG_PER;
            const int cnt   = (start < WG_E) ? min(WG_PER, WG_E - start) : 0;
            for (int g = 0; g < NWG; g++) {
                const int base = g * WG_E + start;
                for (int i = tid; i < cnt; i += 128) {
                    int4 v = w_src[base + i];
                    ((char4*)g_W8)[base + i] =
                        make_char4((signed char)v.x, (signed char)v.y,
                                   (signed char)v.z, (signed char)v.w);
                }
                asm volatile("bar.sync 1, 128;" ::: "memory");
                if (tid == 0) { __threadfence(); atomicAdd(&g_wdone[g], 1); }
            }
        }

        // ======================= EPILOGUE LOOP ================================
        float* s_sc = (float*)(smem + OFF_PRM);
        float* s_zp = s_sc + BN;
        float* s_bi = s_zp + BN;
        for (int ti = 0; ti < ntiles; ti++) {
            const int t  = pair + ti * NPAIR;
            const int mp = t & 15;
            const int cb = (t >> 4) * 256;
            const int row = mp * 256 + rank * 128 + wid * 32 + lane;
            while (ld_acquire(&g_xdone[mp]) < 256) {}   // rowsum/rscale ready
            for (int i = tid; i < BN; i += 128) {
                s_sc[i] = scales[cb + i];
                s_zp[i] = zps[cb + i];
                s_bi[i] = biasv[cb + i];
            }
            asm volatile("bar.sync 1, 128;" ::: "memory");

            mbar_wait(sb + OFF_DONE, ti & 1);
            asm volatile("tcgen05.fence::after_thread_sync;" ::: "memory");

            const float rs  = g_rowsum[row];
            const float srw = g_rscale[row];
            float* orow = out + (size_t)row * OUT_F + cb;

            // double-buffered TMEM drain; EPIF released right after last read
            uint32_t r1a[32], r0a[32], r1b[32], r0b[32];
            TC_LD_X32(r1a, tmem);
            TC_LD_X32(r0a, tmem + 256);
#pragma unroll
            for (int blk = 0; blk < 8; blk++) {
                asm volatile("tcgen05.wait::ld.sync.aligned;" ::: "memory");
                if (blk < 7) {
                    uint32_t* R1n = (blk & 1) ? r1a : r1b;
                    uint32_t* R0n = (blk & 1) ? r0a : r0b;
                    TC_LD_X32(R1n, tmem + (blk + 1) * 32);
                    TC_LD_X32(R0n, tmem + 256 + (blk + 1) * 32);
                } else {
                    asm volatile("tcgen05.fence::before_thread_sync;" ::: "memory");
                    asm volatile("bar.sync 2, 128;" ::: "memory");
                    if (tid == 0) mbar_arrive_rank(sb + OFF_EPIF, 0);
                }
                const uint32_t* R1 = (blk & 1) ? r1b : r1a;
                const uint32_t* R0 = (blk & 1) ? r0b : r0a;
#pragma unroll
                for (int c = 0; c < 32; c += 4) {
                    const int col = blk * 32 + c;
                    float4 v;
#pragma unroll
                    for (int jj = 0; jj < 4; jj++) {
                        const float acc = fmaf(128.f, (float)(int)R1[c + jj],
                                               (float)(int)R0[c + jj]);
                        (&v.x)[jj] = (srw * acc - s_zp[col + jj] * rs) * s_sc[col + jj]
                                     + s_bi[col + jj];
                    }
                    *reinterpret_cast<float4*>(orow + col) = v;
                }
            }
            asm volatile("bar.sync 1, 128;" ::: "memory");
        }
    }

    __syncthreads();
    CLUSTER_SYNC_();   // both CTAs done with TMEM before collective dealloc
    if (wid == 0) {
        asm volatile("tcgen05.dealloc.cta_group::2.sync.aligned.b32 %0, %1;"
                     :: "r"(tmem), "r"(512u));
    }
    CLUSTER_SYNC_();
#else
    (void)tmAh; (void)tmAl; (void)tmB; (void)w_src; (void)x_src;
    (void)scales; (void)zps; (void)biasv; (void)out;
#endif
}

// ============================================================================
// Host launcher
// ============================================================================
typedef CUresult (*tme_fn_t)(CUtensorMap*, CUtensorMapDataType, cuuint32_t, void*,
                             const cuuint64_t*, const cuuint64_t*,
                             const cuuint32_t*, const cuuint32_t*,
                             CUtensorMapInterleave, CUtensorMapSwizzle,
                             CUtensorMapL2promotion, CUtensorMapFloatOOBfill);

extern "C" void kernel_launch(void* const* d_in, const int* in_sizes, int n_in,
                              void* d_out, int out_size) {
    const float* input  = (const float*)d_in[0];
    const int*   w      = (const int*)d_in[1];
    const float* scales = (const float*)d_in[2];
    const float* zps    = (const float*)d_in[3];
    const float* bias   = (const float*)d_in[4];
    float* out = (float*)d_out;
    (void)in_sizes; (void)n_in; (void)out_size;

    void *pW = nullptr, *pAh = nullptr, *pAl = nullptr;
    cudaGetSymbolAddress(&pW,  g_W8);
    cudaGetSymbolAddress(&pAh, g_Ah);
    cudaGetSymbolAddress(&pAl, g_Al);

    tme_fn_t encode = nullptr;
    cudaDriverEntryPointQueryResult qr;
    cudaGetDriverEntryPoint("cuTensorMapEncodeTiled", (void**)&encode,
                            cudaEnableDefault, &qr);

    CUtensorMap mAh, mAl, mB;
    __builtin_memset(&mAh, 0, sizeof(mAh));
    __builtin_memset(&mAl, 0, sizeof(mAl));
    __builtin_memset(&mB, 0, sizeof(mB));
    if (encode) {
        {
            cuuint64_t dims[3]    = { IN_F, TOKENS, 1 };
            cuuint64_t strides[2] = { IN_F, (cuuint64_t)IN_F * TOKENS };
            cuuint32_t box[3]     = { KC, 128, 1 };    // 64B rows (SW64)
            cuuint32_t es[3]      = { 1, 1, 1 };
            encode(&mAh, CU_TENSOR_MAP_DATA_TYPE_UINT8, 3, pAh, dims, strides, box, es,
                   CU_TENSOR_MAP_INTERLEAVE_NONE, CU_TENSOR_MAP_SWIZZLE_64B,
                   CU_TENSOR_MAP_L2_PROMOTION_L2_128B, CU_TENSOR_MAP_FLOAT_OOB_FILL_NONE);
            encode(&mAl, CU_TENSOR_MAP_DATA_TYPE_UINT8, 3, pAl, dims, strides, box, es,
                   CU_TENSOR_MAP_INTERLEAVE_NONE, CU_TENSOR_MAP_SWIZZLE_64B,
                   CU_TENSOR_MAP_L2_PROMOTION_L2_128B, CU_TENSOR_MAP_FLOAT_OOB_FILL_NONE);
        }
        {
            cuuint64_t dims[3]    = { IN_F, OUT_F, 1 };
            cuuint64_t strides[2] = { IN_F, (cuuint64_t)IN_F * OUT_F };
            cuuint32_t box[3]     = { KC, 128, 1 };    // 128-row pieces per CTA
            cuuint32_t es[3]      = { 1, 1, 1 };
            encode(&mB, CU_TENSOR_MAP_DATA_TYPE_UINT8, 3, pW, dims, strides, box, es,
                   CU_TENSOR_MAP_INTERLEAVE_NONE, CU_TENSOR_MAP_SWIZZLE_64B,
                   CU_TENSOR_MAP_L2_PROMOTION_L2_128B, CU_TENSOR_MAP_FLOAT_OOB_FILL_NONE);
        }
    }

    cudaFuncSetAttribute(qlinear_fused, cudaFuncAttributeMaxDynamicSharedMemorySize,
                         SMEM_TOTAL);

    // 1) reset progress counters (graph-replay safe)
    k_zero<<<1, 64>>>();
    // 2) fused prep + persistent GEMM: 148 CTAs = 74 cg2 pairs
    qlinear_fused<<<dim3(2 * NPAIR, 1), 192, SMEM_TOTAL>>>(
        mAh, mAl, mB, (const int4*)w, (const float4*)input,
        scales, zps, bias, out);
}